// round 2
// baseline (speedup 1.0000x reference)
#include <cuda_runtime.h>

#define BB 64
#define CC 64
#define HH 128
#define WW 128

// Scratch (allocation-free rule: __device__ globals)
__device__ float g_cs_e [BB * CC * WW];   // colsum_e [b,c,w]  = sum_h exp(x-m)
__device__ float g_cs_ey[BB * CC * WW];   // colsum_ey[b,c,w]  = sum_h exp(x-m)*wy[h]

// ---------------------------------------------------------------------------
// Pass 1: one CTA per (b,c) slab (128x128 f32 = 64KB), fully register-staged.
//   thread layout: 256 threads = 8 h-subgroups x 32 w-groups (4 consecutive w)
//   each thread loads 16 float4 (rows h = hs + 8r), computes slab max,
//   then exp + column accumulation, deterministic smem tree reduce over hs.
// ---------------------------------------------------------------------------
__global__ __launch_bounds__(256, 2)
void sam_pass1(const float* __restrict__ x) {
    const int bc  = blockIdx.x;                 // 0..4095
    const int tid = threadIdx.x;
    const int wg  = tid & 31;                   // w-group (4 floats)
    const int hs  = tid >> 5;                   // h subgroup 0..7 (== warp id)

    const float4* xp = reinterpret_cast<const float4*>(x)
                     + (size_t)bc * (HH * WW / 4);

    float4 v[16];
#pragma unroll
    for (int r = 0; r < 16; r++)
        v[r] = xp[(hs + 8 * r) * (WW / 4) + wg];

    // ---- slab max ----
    float m = v[0].x;
#pragma unroll
    for (int r = 0; r < 16; r++)
        m = fmaxf(m, fmaxf(fmaxf(v[r].x, v[r].y), fmaxf(v[r].z, v[r].w)));
#pragma unroll
    for (int o = 16; o; o >>= 1)
        m = fmaxf(m, __shfl_xor_sync(0xffffffffu, m, o));

    __shared__ float smax[8];
    if (wg == 0) smax[hs] = m;
    __syncthreads();
#pragma unroll
    for (int k = 0; k < 8; k++) m = fmaxf(m, smax[k]);

    // ---- exp + per-thread column partial sums ----
    const float inv127 = 1.0f / 127.0f;
    float ae0 = 0.f, ae1 = 0.f, ae2 = 0.f, ae3 = 0.f;
    float ay0 = 0.f, ay1 = 0.f, ay2 = 0.f, ay3 = 0.f;
#pragma unroll
    for (int r = 0; r < 16; r++) {
        const float wy = (float)(hs + 8 * r) * inv127;
        float e0 = __expf(v[r].x - m);
        float e1 = __expf(v[r].y - m);
        float e2 = __expf(v[r].z - m);
        float e3 = __expf(v[r].w - m);
        ae0 += e0; ay0 += e0 * wy;
        ae1 += e1; ay1 += e1 * wy;
        ae2 += e2; ay2 += e2 * wy;
        ae3 += e3; ay3 += e3 * wy;
    }

    // ---- deterministic reduce over the 8 h-subgroups ----
    __shared__ float4 se[8][32];   // [hs][wg] -> flat [8][128]
    __shared__ float4 sy[8][32];
    se[hs][wg] = make_float4(ae0, ae1, ae2, ae3);
    sy[hs][wg] = make_float4(ay0, ay1, ay2, ay3);
    __syncthreads();

    if (tid < 128) {
        const float* p = reinterpret_cast<const float*>(se);
        float s = 0.f;
#pragma unroll
        for (int k = 0; k < 8; k++) s += p[k * 128 + tid];
        g_cs_e[(size_t)bc * WW + tid] = s;
    } else {
        const int w = tid - 128;
        const float* p = reinterpret_cast<const float*>(sy);
        float s = 0.f;
#pragma unroll
        for (int k = 0; k < 8; k++) s += p[k * 128 + w];
        g_cs_ey[(size_t)bc * WW + w] = s;
    }
}

// ---------------------------------------------------------------------------
// Pass 2: one CTA per batch b. Compute s[b,w] = sum_c colsum_e, then the
// two dot products per channel. Tiny (4 MB read total, mostly L2-hot).
// ---------------------------------------------------------------------------
__global__ __launch_bounds__(256)
void sam_pass2(float* __restrict__ out) {
    const int b   = blockIdx.x;                 // 0..63
    const int tid = threadIdx.x;

    const float* cse = g_cs_e  + (size_t)b * CC * WW;
    const float* csy = g_cs_ey + (size_t)b * CC * WW;

    __shared__ float rs[WW];
    if (tid < WW) {
        float s = 0.f;
#pragma unroll 8
        for (int c = 0; c < CC; c++) s += cse[c * WW + tid];
        rs[tid] = 1.0f / s;
    }
    __syncthreads();

    const int warp = tid >> 5;
    const int lane = tid & 31;
    const float inv127 = 1.0f / 127.0f;

#pragma unroll
    for (int i = 0; i < 8; i++) {
        const int c = warp * 8 + i;             // 8 warps x 8 channels = 64
        float xx = 0.f, xy = 0.f;
#pragma unroll
        for (int j = 0; j < 4; j++) {
            const int w = lane + 32 * j;
            const float r = rs[w];
            xx += cse[c * WW + w] * ((float)w * inv127) * r;
            xy += csy[c * WW + w] * r;
        }
#pragma unroll
        for (int o = 16; o; o >>= 1) {
            xx += __shfl_xor_sync(0xffffffffu, xx, o);
            xy += __shfl_xor_sync(0xffffffffu, xy, o);
        }
        if (lane == 0) {
            out[((size_t)b * CC + c) * 2 + 0] = xx;
            out[((size_t)b * CC + c) * 2 + 1] = xy;
        }
    }
}

extern "C" void kernel_launch(void* const* d_in, const int* in_sizes, int n_in,
                              void* d_out, int out_size) {
    const float* x = (const float*)d_in[0];
    float* out = (float*)d_out;
    sam_pass1<<<BB * CC, 256>>>(x);
    sam_pass2<<<BB, 256>>>(out);
}

// round 3
// speedup vs baseline: 1.1137x; 1.1137x over previous
#include <cuda_runtime.h>

#define BB 64
#define CC 64
#define HH 128
#define WW 128

// Scratch (allocation-free rule: __device__ globals)
__device__ float g_cs_e [BB * CC * WW];   // colsum_e [b,c,w]  = sum_h exp(x-m)
__device__ float g_cs_ey[BB * CC * WW];   // colsum_ey[b,c,w]  = sum_h exp(x-m)*wy[h]

// ---------------------------------------------------------------------------
// Pass 1: one CTA per (b,c) slab (128x128 f32 = 64KB), register-staged.
//   512 threads = 16 h-subgroups x 32 w-groups (4 consecutive w each).
//   Each thread loads 8 float4 (rows h = hs + 16r): 32 data regs -> ~55 regs
//   total -> 2 CTAs (1024 threads) resident per SM for DRAM latency hiding.
// ---------------------------------------------------------------------------
__global__ __launch_bounds__(512, 2)
void sam_pass1(const float* __restrict__ x) {
    const int bc  = blockIdx.x;                 // 0..4095
    const int tid = threadIdx.x;
    const int wg  = tid & 31;                   // w-group (4 floats)
    const int hs  = tid >> 5;                   // h subgroup 0..15 (== warp id)

    const float4* xp = reinterpret_cast<const float4*>(x)
                     + (size_t)bc * (HH * WW / 4);

    float4 v[8];
#pragma unroll
    for (int r = 0; r < 8; r++)
        v[r] = xp[(hs + 16 * r) * (WW / 4) + wg];

    // ---- slab max ----
    float m = v[0].x;
#pragma unroll
    for (int r = 0; r < 8; r++)
        m = fmaxf(m, fmaxf(fmaxf(v[r].x, v[r].y), fmaxf(v[r].z, v[r].w)));
#pragma unroll
    for (int o = 16; o; o >>= 1)
        m = fmaxf(m, __shfl_xor_sync(0xffffffffu, m, o));

    __shared__ float smax[16];
    if (wg == 0) smax[hs] = m;
    __syncthreads();
#pragma unroll
    for (int k = 0; k < 16; k++) m = fmaxf(m, smax[k]);

    // ---- exp + per-thread column partial sums ----
    const float inv127 = 1.0f / 127.0f;
    float ae0 = 0.f, ae1 = 0.f, ae2 = 0.f, ae3 = 0.f;
    float ay0 = 0.f, ay1 = 0.f, ay2 = 0.f, ay3 = 0.f;
#pragma unroll
    for (int r = 0; r < 8; r++) {
        const float wy = (float)(hs + 16 * r) * inv127;
        float e0 = __expf(v[r].x - m);
        float e1 = __expf(v[r].y - m);
        float e2 = __expf(v[r].z - m);
        float e3 = __expf(v[r].w - m);
        ae0 += e0; ay0 += e0 * wy;
        ae1 += e1; ay1 += e1 * wy;
        ae2 += e2; ay2 += e2 * wy;
        ae3 += e3; ay3 += e3 * wy;
    }

    // ---- deterministic reduce over the 16 h-subgroups ----
    __shared__ float4 se[16][32];   // [hs][wg] -> flat [16][128]
    __shared__ float4 sy[16][32];
    se[hs][wg] = make_float4(ae0, ae1, ae2, ae3);
    sy[hs][wg] = make_float4(ay0, ay1, ay2, ay3);
    __syncthreads();

    if (tid < 128) {
        const float* p = reinterpret_cast<const float*>(se);
        float s = 0.f;
#pragma unroll
        for (int k = 0; k < 16; k++) s += p[k * 128 + tid];
        g_cs_e[(size_t)bc * WW + tid] = s;
    } else if (tid < 256) {
        const int w = tid - 128;
        const float* p = reinterpret_cast<const float*>(sy);
        float s = 0.f;
#pragma unroll
        for (int k = 0; k < 16; k++) s += p[k * 128 + w];
        g_cs_ey[(size_t)bc * WW + w] = s;
    }
}

// ---------------------------------------------------------------------------
// Pass 2: one CTA per batch b, 1024 threads.
//   Phase A: s[b,w] = sum_c colsum_e  -- 8 c-groups x 128 w, 8 loads/thread,
//            all coalesced and L2-hot, smem combine.
//   Phase B: 32 warps x 2 channels each -> the two 128-wide dot products.
// ---------------------------------------------------------------------------
__global__ __launch_bounds__(1024)
void sam_pass2(float* __restrict__ out) {
    const int b   = blockIdx.x;                 // 0..63
    const int tid = threadIdx.x;

    const float* __restrict__ cse = g_cs_e  + (size_t)b * CC * WW;
    const float* __restrict__ csy = g_cs_ey + (size_t)b * CC * WW;

    __shared__ float sA[8][WW];
    __shared__ float rs[WW];

    // Phase A: partial sums over c (8 groups of 8 channels)
    {
        const int w  = tid & 127;
        const int cg = tid >> 7;                // 0..7
        float s = 0.f;
#pragma unroll
        for (int k = 0; k < 8; k++)
            s += cse[(cg + 8 * k) * WW + w];
        sA[cg][w] = s;
    }
    __syncthreads();
    if (tid < WW) {
        float s = 0.f;
#pragma unroll
        for (int k = 0; k < 8; k++) s += sA[k][tid];
        rs[tid] = 1.0f / s;
    }
    __syncthreads();

    // Phase B: per-channel dot products, 2 channels per warp
    const int warp = tid >> 5;                  // 0..31
    const int lane = tid & 31;
    const float inv127 = 1.0f / 127.0f;

#pragma unroll
    for (int i = 0; i < 2; i++) {
        const int c = warp * 2 + i;             // 0..63
        float xx = 0.f, xy = 0.f;
#pragma unroll
        for (int j = 0; j < 4; j++) {
            const int w = lane + 32 * j;
            const float r = rs[w];
            xx += cse[c * WW + w] * ((float)w * inv127) * r;
            xy += csy[c * WW + w] * r;
        }
#pragma unroll
        for (int o = 16; o; o >>= 1) {
            xx += __shfl_xor_sync(0xffffffffu, xx, o);
            xy += __shfl_xor_sync(0xffffffffu, xy, o);
        }
        if (lane == 0) {
            out[((size_t)b * CC + c) * 2 + 0] = xx;
            out[((size_t)b * CC + c) * 2 + 1] = xy;
        }
    }
}

extern "C" void kernel_launch(void* const* d_in, const int* in_sizes, int n_in,
                              void* d_out, int out_size) {
    const float* x = (const float*)d_in[0];
    float* out = (float*)d_out;
    sam_pass1<<<BB * CC, 512>>>(x);
    sam_pass2<<<BB, 1024>>>(out);
}